// round 5
// baseline (speedup 1.0000x reference)
#include <cuda_runtime.h>
#include <cuda_bf16.h>
#include <cstdint>

// Problem constants
#define BB   16
#define SS   577
#define DD   1408
#define HH   16
#define HD   88
#define SCALE_F 0.10660035817780521f  // 1/sqrt(88)

#define MM   (BB * SS)      // 9232
#define N1   (3 * DD)       // 4224
#define KK   DD             // 1408

// ---------------------------------------------------------------------------
// Device-global scratch
// ---------------------------------------------------------------------------
__device__ __nv_bfloat16 g_hsH[(size_t)MM * KK];
__device__ __nv_bfloat16 g_hsL[(size_t)MM * KK];
__device__ __nv_bfloat16 g_qkvH[(size_t)MM * N1];
__device__ __nv_bfloat16 g_qkvL[(size_t)MM * N1];
__device__ __nv_bfloat16 g_attH[(size_t)MM * KK];
__device__ __nv_bfloat16 g_attL[(size_t)MM * KK];
__device__ __nv_bfloat16 g_wqkvH[(size_t)N1 * KK];   // transposed [N,K]
__device__ __nv_bfloat16 g_wqkvL[(size_t)N1 * KK];
__device__ __nv_bfloat16 g_wprojH[(size_t)DD * KK];  // transposed [N,K]
__device__ __nv_bfloat16 g_wprojL[(size_t)DD * KK];

// ---------------------------------------------------------------------------
// PTX helpers (sm_80+ only; harness targets sm_103 w/o 'a' — no tcgen05)
// ---------------------------------------------------------------------------
__device__ __forceinline__ uint32_t smem_to_u32(const void* p) {
    uint32_t a;
    asm("{ .reg .u64 t; cvta.to.shared.u64 t, %1; cvt.u32.u64 %0, t; }"
        : "=r"(a) : "l"(p));
    return a;
}
__device__ __forceinline__ void cp16(uint32_t dst, const void* src, uint32_t sz) {
    asm volatile("cp.async.ca.shared.global [%0], [%1], 16, %2;"
                 :: "r"(dst), "l"(src), "r"(sz) : "memory");
}
#define CP_COMMIT() asm volatile("cp.async.commit_group;" ::: "memory")
#define CP_WAIT(n)  asm volatile("cp.async.wait_group %0;" :: "n"(n) : "memory")

__device__ __forceinline__ void ldsm_x4(uint32_t* r, uint32_t addr) {
    asm volatile("ldmatrix.sync.aligned.m8n8.x4.shared.b16 {%0,%1,%2,%3}, [%4];"
                 : "=r"(r[0]), "=r"(r[1]), "=r"(r[2]), "=r"(r[3]) : "r"(addr));
}
__device__ __forceinline__ void ldsm_x2(uint32_t* r, uint32_t addr) {
    asm volatile("ldmatrix.sync.aligned.m8n8.x2.shared.b16 {%0,%1}, [%2];"
                 : "=r"(r[0]), "=r"(r[1]) : "r"(addr));
}
__device__ __forceinline__ void ldsm_x2t(uint32_t* r, uint32_t addr) {
    asm volatile("ldmatrix.sync.aligned.m8n8.x2.trans.shared.b16 {%0,%1}, [%2];"
                 : "=r"(r[0]), "=r"(r[1]) : "r"(addr));
}
__device__ __forceinline__ void mma16816(float* d, const uint32_t* a, const uint32_t* b) {
    asm volatile("mma.sync.aligned.m16n8k16.row.col.f32.bf16.bf16.f32 "
                 "{%0,%1,%2,%3}, {%4,%5,%6,%7}, {%8,%9}, {%0,%1,%2,%3};"
                 : "+f"(d[0]), "+f"(d[1]), "+f"(d[2]), "+f"(d[3])
                 : "r"(a[0]), "r"(a[1]), "r"(a[2]), "r"(a[3]), "r"(b[0]), "r"(b[1]));
}
__device__ __forceinline__ void split_pair(float a, float b, uint32_t& hi, uint32_t& lo) {
    __nv_bfloat16 ha = __float2bfloat16(a), hb = __float2bfloat16(b);
    float la = a - __bfloat162float(ha), lb = b - __bfloat162float(hb);
    __nv_bfloat16 hla = __float2bfloat16(la), hlb = __float2bfloat16(lb);
    hi = ((uint32_t)*(uint16_t*)&hb << 16) | *(uint16_t*)&ha;
    lo = ((uint32_t)*(uint16_t*)&hlb << 16) | *(uint16_t*)&hla;
}

// ---------------------------------------------------------------------------
// Split fp32 -> (hi, lo) bf16, same layout.
// ---------------------------------------------------------------------------
__global__ void split_kernel(const float4* __restrict__ in,
                             uint2* __restrict__ hi, uint2* __restrict__ lo, int n4)
{
    int i = blockIdx.x * blockDim.x + threadIdx.x;
    if (i >= n4) return;
    float4 v = in[i];
    uint2 ho, loo;
    split_pair(v.x, v.y, ho.x, loo.x);
    split_pair(v.z, v.w, ho.y, loo.y);
    hi[i] = ho;
    lo[i] = loo;
}

// ---------------------------------------------------------------------------
// Transpose + split: in fp32 [R, C] -> hi/lo bf16 [C, R]
// ---------------------------------------------------------------------------
__global__ void tsplit_kernel(const float* __restrict__ in,
                              __nv_bfloat16* __restrict__ hi,
                              __nv_bfloat16* __restrict__ lo, int R, int C)
{
    __shared__ float t[32][33];
    int c0 = blockIdx.x * 32, r0 = blockIdx.y * 32;
    int tx = threadIdx.x, ty = threadIdx.y;
#pragma unroll
    for (int i = ty; i < 32; i += 8)
        t[i][tx] = in[(size_t)(r0 + i) * C + c0 + tx];
    __syncthreads();
#pragma unroll
    for (int i = ty; i < 32; i += 8) {
        float x = t[tx][i];
        __nv_bfloat16 h = __float2bfloat16(x);
        __nv_bfloat16 l = __float2bfloat16(x - __bfloat162float(h));
        size_t off = (size_t)(c0 + i) * R + r0 + tx;
        hi[off] = h;
        lo[off] = l;
    }
}

// ---------------------------------------------------------------------------
// bf16x3-split MMA GEMM: C[M,N] = A[M,K] @ B[N,K]^T + bias[N]
// MODE 0: fp32 C out.  MODE 1: bf16 hi/lo out, cols<DD scaled by SCALE_F.
// MMA issue order: per split-term across all accumulators (16 independent
// MMAs between dependent reuses) to cover HMMA latency.
// ---------------------------------------------------------------------------
#define BK      32
#define STAGES  3
#define TBYTES  8192
#define STAGE_BYTES (4 * TBYTES)
#define NCH     (KK / BK)

__device__ __forceinline__ uint32_t swz(int r, int c) {
    return (uint32_t)(r * 64 + ((c ^ ((r >> 1) & 3)) << 4));
}

template<int MODE>
__global__ __launch_bounds__(256, 1) void gemm_mma_kernel(
    const __nv_bfloat16* __restrict__ Ahi, const __nv_bfloat16* __restrict__ Alo,
    const __nv_bfloat16* __restrict__ Bhi, const __nv_bfloat16* __restrict__ Blo,
    const float* __restrict__ bias, float* __restrict__ C,
    __nv_bfloat16* __restrict__ CH, __nv_bfloat16* __restrict__ CL,
    int M, int N)
{
    extern __shared__ char smem[];
    const uint32_t sbase = smem_to_u32(smem);

    const int tid = threadIdx.x;
    const int lane = tid & 31;
    const int wid = tid >> 5;
    const int wm = wid & 3;
    const int wn = wid >> 2;
    const int m0 = blockIdx.y * 128;
    const int n0 = blockIdx.x * 128;

    auto load_stage = [&](int kt, int slot) {
        const int k0 = kt * BK;
        const uint32_t st = sbase + slot * STAGE_BYTES;
#pragma unroll
        for (int i = 0; i < 8; ++i) {
            int idx = tid + i * 256;
            int tile = idx >> 9;
            int rem = idx & 511;
            int r = rem >> 2;
            int c = rem & 3;
            uint32_t dst = st + tile * TBYTES + swz(r, c);
            const __nv_bfloat16* gp;
            uint32_t sz = 16;
            if (tile < 2) {
                int m = m0 + r;
                int mc = m < M ? m : 0;
                if (m >= M) sz = 0;
                gp = (tile == 0 ? Ahi : Alo) + (size_t)mc * KK + k0 + c * 8;
            } else {
                int n = n0 + r;
                gp = (tile == 2 ? Bhi : Blo) + (size_t)n * KK + k0 + c * 8;
            }
            cp16(dst, gp, sz);
        }
        CP_COMMIT();
    };

    float acc[2][8][4];
#pragma unroll
    for (int t = 0; t < 2; ++t)
#pragma unroll
        for (int j = 0; j < 8; ++j)
#pragma unroll
            for (int v = 0; v < 4; ++v) acc[t][j][v] = 0.f;

    load_stage(0, 0);
    load_stage(1, 1);

    for (int kt = 0; kt < NCH; ++kt) {
        CP_WAIT(1);
        __syncthreads();
        if (kt + 2 < NCH) load_stage(kt + 2, (kt + 2) % STAGES);

        const uint32_t st = sbase + (kt % STAGES) * STAGE_BYTES;
#pragma unroll
        for (int ks = 0; ks < 2; ++ks) {
            uint32_t ah[2][4], al[2][4], bh[8][2], bl[8][2];
#pragma unroll
            for (int t = 0; t < 2; ++t) {
                int r = wm * 32 + t * 16 + (lane & 15);
                int c = ks * 2 + (lane >> 4);
                uint32_t off = swz(r, c);
                ldsm_x4(ah[t], st + 0 * TBYTES + off);
                ldsm_x4(al[t], st + 1 * TBYTES + off);
            }
#pragma unroll
            for (int j = 0; j < 8; ++j) {
                int r = wn * 64 + j * 8 + (lane & 7);
                int c = ks * 2 + ((lane >> 3) & 1);
                uint32_t off = swz(r, c);
                ldsm_x2(bh[j], st + 2 * TBYTES + off);
                ldsm_x2(bl[j], st + 3 * TBYTES + off);
            }
            // term-major issue: 16 independent MMAs between acc reuses
#pragma unroll
            for (int t = 0; t < 2; ++t)
#pragma unroll
                for (int j = 0; j < 8; ++j)
                    mma16816(acc[t][j], ah[t], bh[j]);
#pragma unroll
            for (int t = 0; t < 2; ++t)
#pragma unroll
                for (int j = 0; j < 8; ++j)
                    mma16816(acc[t][j], ah[t], bl[j]);
#pragma unroll
            for (int t = 0; t < 2; ++t)
#pragma unroll
                for (int j = 0; j < 8; ++j)
                    mma16816(acc[t][j], al[t], bh[j]);
        }
    }

    const int rb = m0 + wm * 32 + (lane >> 2);
    const int cb = n0 + wn * 64 + (lane & 3) * 2;
#pragma unroll
    for (int t = 0; t < 2; ++t) {
        int r0 = rb + t * 16;
#pragma unroll
        for (int j = 0; j < 8; ++j) {
            int col = cb + j * 8;
            float2 b2 = *(const float2*)&bias[col];
            if constexpr (MODE == 0) {
                if (r0 < M) {
                    float2 o = {acc[t][j][0] + b2.x, acc[t][j][1] + b2.y};
                    *(float2*)&C[(size_t)r0 * N + col] = o;
                }
                if (r0 + 8 < M) {
                    float2 o = {acc[t][j][2] + b2.x, acc[t][j][3] + b2.y};
                    *(float2*)&C[(size_t)(r0 + 8) * N + col] = o;
                }
            } else {
                float s = (col < DD) ? SCALE_F : 1.0f;
                if (r0 < M) {
                    uint32_t hi, lo;
                    split_pair((acc[t][j][0] + b2.x) * s, (acc[t][j][1] + b2.y) * s, hi, lo);
                    *(uint32_t*)&CH[(size_t)r0 * N + col] = hi;
                    *(uint32_t*)&CL[(size_t)r0 * N + col] = lo;
                }
                if (r0 + 8 < M) {
                    uint32_t hi, lo;
                    split_pair((acc[t][j][2] + b2.x) * s, (acc[t][j][3] + b2.y) * s, hi, lo);
                    *(uint32_t*)&CH[(size_t)(r0 + 8) * N + col] = hi;
                    *(uint32_t*)&CL[(size_t)(r0 + 8) * N + col] = lo;
                }
            }
        }
    }
}

// ---------------------------------------------------------------------------
// Tensor-core flash attention (term-major MMA issue).
// ---------------------------------------------------------------------------
#define SM_QH   0
#define SM_QL   24576
#define SM_KV   49152
#define SM_PH   147456
#define SM_PL   163840
#define SM_STAT 180224
#define SM_ATT_TOTAL 182272

__device__ __forceinline__ uint32_t swzQ(int r, int c) {
    return (uint32_t)(r * 192 + ((c ^ ((r >> 1) & 3)) << 4));
}
__device__ __forceinline__ uint32_t swzP(int r, int c) {
    return (uint32_t)(r * 128 + ((c ^ (r & 7)) << 4));
}

__global__ __launch_bounds__(256, 1) void attn_tc_kernel(
    const __nv_bfloat16* __restrict__ qkvH, const __nv_bfloat16* __restrict__ qkvL,
    __nv_bfloat16* __restrict__ attH, __nv_bfloat16* __restrict__ attL)
{
    extern __shared__ char smem[];
    const uint32_t sb = smem_to_u32(smem);
    const int tid = threadIdx.x;
    const int lane = tid & 31;
    const int wid = tid >> 5;
    const int wm = wid & 3;
    const int wn = wid >> 2;
    const int b = blockIdx.z;
    const int h = blockIdx.y;
    const int q0 = blockIdx.x * 128;

    float* sMax = (float*)(smem + SM_STAT);
    float* sSum = (float*)(smem + SM_STAT + 1024);

    const size_t rowbase = (size_t)b * SS * N1 + (size_t)h * HD;

    {
        int r = tid >> 1;
        int cbase = (tid & 1) * 6;
        int s = q0 + r;
        int sc_ = s < SS ? s : SS - 1;
        const __nv_bfloat16* srcH = qkvH + rowbase + (size_t)sc_ * N1;
        const __nv_bfloat16* srcL = qkvL + rowbase + (size_t)sc_ * N1;
#pragma unroll
        for (int cc = 0; cc < 6; ++cc) {
            int c = cbase + cc;
            int ca = c < 11 ? c : 10;
            uint32_t sz = (c < 11 && s < SS) ? 16 : 0;
            cp16(sb + SM_QH + swzQ(r, c), srcH + ca * 8, sz);
            cp16(sb + SM_QL + swzQ(r, c), srcL + ca * 8, sz);
        }
    }

    auto load_kv = [&](int kt, int buf) {
        int r = tid >> 2;
        int cbase = (tid & 3) * 3;
        int s = kt * 64 + r;
        int sc_ = s < SS ? s : SS - 1;
        const uint32_t kb = sb + SM_KV + buf * 49152;
        const __nv_bfloat16* base[4] = {
            qkvH + rowbase + (size_t)sc_ * N1 + DD,
            qkvL + rowbase + (size_t)sc_ * N1 + DD,
            qkvH + rowbase + (size_t)sc_ * N1 + 2 * DD,
            qkvL + rowbase + (size_t)sc_ * N1 + 2 * DD
        };
#pragma unroll
        for (int arr = 0; arr < 4; ++arr) {
#pragma unroll
            for (int cc = 0; cc < 3; ++cc) {
                int c = cbase + cc;
                int ca = c < 11 ? c : 10;
                uint32_t sz = (c < 11 && s < SS) ? 16 : 0;
                cp16(kb + arr * 12288 + swzQ(r, c), base[arr] + ca * 8, sz);
            }
        }
    };

    load_kv(0, 0);
    CP_COMMIT();

    float acc[2][6][4];
#pragma unroll
    for (int ti = 0; ti < 2; ++ti)
#pragma unroll
        for (int j = 0; j < 6; ++j)
#pragma unroll
            for (int v = 0; v < 4; ++v) acc[ti][j][v] = 0.f;
    float m_old[2][2] = {{-1e30f, -1e30f}, {-1e30f, -1e30f}};
    float l_run[2][2] = {{0.f, 0.f}, {0.f, 0.f}};

    const int NKT = (SS + 63) / 64;

    for (int kt = 0; kt < NKT; ++kt) {
        CP_WAIT(0);
        __syncthreads();
        if (kt + 1 < NKT) load_kv(kt + 1, (kt + 1) & 1);
        CP_COMMIT();

        const uint32_t kb = sb + SM_KV + (kt & 1) * 49152;

        // ---- QK^T ----
        float sc[2][4][4];
#pragma unroll
        for (int ti = 0; ti < 2; ++ti)
#pragma unroll
            for (int j = 0; j < 4; ++j)
#pragma unroll
                for (int v = 0; v < 4; ++v) sc[ti][j][v] = 0.f;

#pragma unroll
        for (int ks = 0; ks < 6; ++ks) {
            uint32_t ah[2][4], al[2][4], bh[4][2], bl[4][2];
#pragma unroll
            for (int ti = 0; ti < 2; ++ti) {
                int r = wm * 32 + ti * 16 + (lane & 15);
                int c = ks * 2 + (lane >> 4);
                uint32_t off = swzQ(r, c);
                ldsm_x4(ah[ti], sb + SM_QH + off);
                ldsm_x4(al[ti], sb + SM_QL + off);
            }
#pragma unroll
            for (int j = 0; j < 4; ++j) {
                int r = wn * 32 + j * 8 + (lane & 7);
                int c = ks * 2 + ((lane >> 3) & 1);
                uint32_t off = swzQ(r, c);
                ldsm_x2(bh[j], kb + 0 + off);
                ldsm_x2(bl[j], kb + 12288 + off);
            }
#pragma unroll
            for (int ti = 0; ti < 2; ++ti)
#pragma unroll
                for (int j = 0; j < 4; ++j)
                    mma16816(sc[ti][j], ah[ti], bh[j]);
#pragma unroll
            for (int ti = 0; ti < 2; ++ti)
#pragma unroll
                for (int j = 0; j < 4; ++j)
                    mma16816(sc[ti][j], ah[ti], bl[j]);
#pragma unroll
            for (int ti = 0; ti < 2; ++ti)
#pragma unroll
                for (int j = 0; j < 4; ++j)
                    mma16816(sc[ti][j], al[ti], bh[j]);
        }

        // ---- mask ----
#pragma unroll
        for (int j = 0; j < 4; ++j) {
            int c0 = kt * 64 + wn * 32 + j * 8 + (lane & 3) * 2;
            if (c0 >= SS) { sc[0][j][0] = sc[0][j][2] = sc[1][j][0] = sc[1][j][2] = -1e30f; }
            if (c0 + 1 >= SS) { sc[0][j][1] = sc[0][j][3] = sc[1][j][1] = sc[1][j][3] = -1e30f; }
        }

        // ---- row max ----
#pragma unroll
        for (int ti = 0; ti < 2; ++ti)
#pragma unroll
            for (int hh = 0; hh < 2; ++hh) {
                float mt = -1e30f;
#pragma unroll
                for (int j = 0; j < 4; ++j)
                    mt = fmaxf(mt, fmaxf(sc[ti][j][hh * 2], sc[ti][j][hh * 2 + 1]));
                mt = fmaxf(mt, __shfl_xor_sync(0xffffffffu, mt, 1));
                mt = fmaxf(mt, __shfl_xor_sync(0xffffffffu, mt, 2));
                if ((lane & 3) == 0) {
                    int rl = wm * 32 + ti * 16 + hh * 8 + (lane >> 2);
                    sMax[wn * 128 + rl] = mt;
                }
            }
        __syncthreads();

        float mnew[2][2], corr[2][2];
#pragma unroll
        for (int ti = 0; ti < 2; ++ti)
#pragma unroll
            for (int hh = 0; hh < 2; ++hh) {
                int rl = wm * 32 + ti * 16 + hh * 8 + (lane >> 2);
                float m2 = fmaxf(sMax[rl], sMax[128 + rl]);
                float mn = fmaxf(m_old[ti][hh], m2);
                corr[ti][hh] = __expf(m_old[ti][hh] - mn);
                mnew[ti][hh] = mn;
                m_old[ti][hh] = mn;
            }

        // ---- exp, P store, sums ----
        float sum_[2][2] = {{0.f, 0.f}, {0.f, 0.f}};
#pragma unroll
        for (int ti = 0; ti < 2; ++ti) {
            int r0 = wm * 32 + ti * 16 + (lane >> 2);
#pragma unroll
            for (int j = 0; j < 4; ++j) {
                float p0 = __expf(sc[ti][j][0] - mnew[ti][0]);
                float p1 = __expf(sc[ti][j][1] - mnew[ti][0]);
                float p2 = __expf(sc[ti][j][2] - mnew[ti][1]);
                float p3 = __expf(sc[ti][j][3] - mnew[ti][1]);
                sum_[ti][0] += p0 + p1;
                sum_[ti][1] += p2 + p3;
                int colc = wn * 32 + j * 8 + (lane & 3) * 2;
                uint32_t o0 = swzP(r0, colc >> 3) + (colc & 7) * 2;
                uint32_t o1 = swzP(r0 + 8, colc >> 3) + (colc & 7) * 2;
                uint32_t hi, lo;
                split_pair(p0, p1, hi, lo);
                *(uint32_t*)(smem + SM_PH + o0) = hi;
                *(uint32_t*)(smem + SM_PL + o0) = lo;
                split_pair(p2, p3, hi, lo);
                *(uint32_t*)(smem + SM_PH + o1) = hi;
                *(uint32_t*)(smem + SM_PL + o1) = lo;
            }
        }
#pragma unroll
        for (int ti = 0; ti < 2; ++ti)
#pragma unroll
            for (int hh = 0; hh < 2; ++hh) {
                float s = sum_[ti][hh];
                s += __shfl_xor_sync(0xffffffffu, s, 1);
                s += __shfl_xor_sync(0xffffffffu, s, 2);
                if ((lane & 3) == 0) {
                    int rl = wm * 32 + ti * 16 + hh * 8 + (lane >> 2);
                    sSum[wn * 128 + rl] = s;
                }
            }
#pragma unroll
        for (int ti = 0; ti < 2; ++ti)
#pragma unroll
            for (int j = 0; j < 6; ++j) {
                acc[ti][j][0] *= corr[ti][0];
                acc[ti][j][1] *= corr[ti][0];
                acc[ti][j][2] *= corr[ti][1];
                acc[ti][j][3] *= corr[ti][1];
            }
        __syncthreads();
#pragma unroll
        for (int ti = 0; ti < 2; ++ti)
#pragma unroll
            for (int hh = 0; hh < 2; ++hh) {
                int rl = wm * 32 + ti * 16 + hh * 8 + (lane >> 2);
                l_run[ti][hh] = l_run[ti][hh] * corr[ti][hh] + sSum[rl] + sSum[128 + rl];
            }

        // ---- P.V ----
#pragma unroll
        for (int ks = 0; ks < 4; ++ks) {
            uint32_t ph[2][4], pl[2][4], vh[6][2], vl[6][2];
#pragma unroll
            for (int ti = 0; ti < 2; ++ti) {
                int r = wm * 32 + ti * 16 + (lane & 15);
                int c = ks * 2 + (lane >> 4);
                uint32_t off = swzP(r, c);
                ldsm_x4(ph[ti], sb + SM_PH + off);
                ldsm_x4(pl[ti], sb + SM_PL + off);
            }
#pragma unroll
            for (int j = 0; j < 6; ++j) {
                int rk = ks * 16 + (lane & 15);
                int c = wn * 6 + j;
                uint32_t off = swzQ(rk, c);
                ldsm_x2t(vh[j], kb + 24576 + off);
                ldsm_x2t(vl[j], kb + 36864 + off);
            }
#pragma unroll
            for (int ti = 0; ti < 2; ++ti)
#pragma unroll
                for (int j = 0; j < 6; ++j)
                    mma16816(acc[ti][j], ph[ti], vh[j]);
#pragma unroll
            for (int ti = 0; ti < 2; ++ti)
#pragma unroll
                for (int j = 0; j < 6; ++j)
                    mma16816(acc[ti][j], ph[ti], vl[j]);
#pragma unroll
            for (int ti = 0; ti < 2; ++ti)
#pragma unroll
                for (int j = 0; j < 6; ++j)
                    mma16816(acc[ti][j], pl[ti], vh[j]);
        }
    }

    // ---- epilogue ----
    float inv[2][2];
#pragma unroll
    for (int ti = 0; ti < 2; ++ti)
#pragma unroll
        for (int hh = 0; hh < 2; ++hh)
            inv[ti][hh] = 1.f / l_run[ti][hh];

#pragma unroll
    for (int ti = 0; ti < 2; ++ti)
#pragma unroll
        for (int j = 0; j < 6; ++j) {
            int col = wn * 48 + j * 8 + (lane & 3) * 2;
            if (col >= HD) continue;
#pragma unroll
            for (int hh = 0; hh < 2; ++hh) {
                int s = q0 + wm * 32 + ti * 16 + hh * 8 + (lane >> 2);
                if (s >= SS) continue;
                float o0 = acc[ti][j][hh * 2] * inv[ti][hh];
                float o1 = acc[ti][j][hh * 2 + 1] * inv[ti][hh];
                uint32_t hi, lo;
                split_pair(o0, o1, hi, lo);
                size_t off = (size_t)(b * SS + s) * KK + (size_t)h * HD + col;
                *(uint32_t*)&attH[off] = hi;
                *(uint32_t*)&attL[off] = lo;
            }
        }
}

// ---------------------------------------------------------------------------
extern "C" void kernel_launch(void* const* d_in, const int* in_sizes, int n_in,
                              void* d_out, int out_size)
{
    const float* hs     = (const float*)d_in[0];
    const float* w_qkv  = (const float*)d_in[1];
    const float* b_qkv  = (const float*)d_in[2];
    const float* w_proj = (const float*)d_in[3];
    const float* b_proj = (const float*)d_in[4];
    float* out = (float*)d_out;

    __nv_bfloat16 *hsH, *hsL, *qkvH, *qkvL, *attH, *attL, *wqH, *wqL, *wpH, *wpL;
    cudaGetSymbolAddress((void**)&hsH, g_hsH);
    cudaGetSymbolAddress((void**)&hsL, g_hsL);
    cudaGetSymbolAddress((void**)&qkvH, g_qkvH);
    cudaGetSymbolAddress((void**)&qkvL, g_qkvL);
    cudaGetSymbolAddress((void**)&attH, g_attH);
    cudaGetSymbolAddress((void**)&attL, g_attL);
    cudaGetSymbolAddress((void**)&wqH, g_wqkvH);
    cudaGetSymbolAddress((void**)&wqL, g_wqkvL);
    cudaGetSymbolAddress((void**)&wpH, g_wprojH);
    cudaGetSymbolAddress((void**)&wpL, g_wprojL);

    const int gemm_smem = STAGES * STAGE_BYTES;   // 96 KB
    cudaFuncSetAttribute(gemm_mma_kernel<0>, cudaFuncAttributeMaxDynamicSharedMemorySize, gemm_smem);
    cudaFuncSetAttribute(gemm_mma_kernel<1>, cudaFuncAttributeMaxDynamicSharedMemorySize, gemm_smem);
    cudaFuncSetAttribute(attn_tc_kernel, cudaFuncAttributeMaxDynamicSharedMemorySize, SM_ATT_TOTAL);

    // 0a) split hidden_states
    {
        int n4 = MM * KK / 4;
        split_kernel<<<(n4 + 255) / 256, 256>>>((const float4*)hs, (uint2*)hsH, (uint2*)hsL, n4);
    }
    // 0b) transpose+split weights
    {
        dim3 g(N1 / 32, KK / 32);
        tsplit_kernel<<<g, dim3(32, 8)>>>(w_qkv, wqH, wqL, KK, N1);
    }
    {
        dim3 g(DD / 32, KK / 32);
        tsplit_kernel<<<g, dim3(32, 8)>>>(w_proj, wpH, wpL, KK, DD);
    }
    // 1) QKV projection -> bf16 hi/lo (q pre-scaled)
    {
        dim3 g(N1 / 128, (MM + 127) / 128);
        gemm_mma_kernel<1><<<g, 256, gemm_smem>>>(hsH, hsL, wqH, wqL, b_qkv,
                                                  nullptr, qkvH, qkvL, MM, N1);
    }
    // 2) tensor-core flash attention -> bf16 hi/lo
    {
        dim3 g((SS + 127) / 128, HH, BB);
        attn_tc_kernel<<<g, 256, SM_ATT_TOTAL>>>(qkvH, qkvL, attH, attL);
    }
    // 3) output projection -> fp32
    {
        dim3 g(DD / 128, (MM + 127) / 128);
        gemm_mma_kernel<0><<<g, 256, gemm_smem>>>(attH, attL, wpH, wpL, b_proj,
                                                  out, nullptr, nullptr, MM, DD);
    }
}

// round 6
// speedup vs baseline: 1.0302x; 1.0302x over previous
#include <cuda_runtime.h>
#include <cuda_bf16.h>
#include <cstdint>

// Problem constants
#define BB   16
#define SS   577
#define DD   1408
#define HH   16
#define HD   88
#define SCALE_F 0.10660035817780521f  // 1/sqrt(88)

#define MM   (BB * SS)      // 9232
#define N1   (3 * DD)       // 4224
#define KK   DD             // 1408

// ---------------------------------------------------------------------------
// Device-global scratch
// ---------------------------------------------------------------------------
__device__ __nv_bfloat16 g_hsH[(size_t)MM * KK];
__device__ __nv_bfloat16 g_hsL[(size_t)MM * KK];
__device__ __nv_bfloat16 g_qkvH[(size_t)MM * N1];
__device__ __nv_bfloat16 g_qkvL[(size_t)MM * N1];
__device__ __nv_bfloat16 g_attH[(size_t)MM * KK];
__device__ __nv_bfloat16 g_attL[(size_t)MM * KK];
__device__ __nv_bfloat16 g_wqkvH[(size_t)N1 * KK];   // transposed [N,K]
__device__ __nv_bfloat16 g_wqkvL[(size_t)N1 * KK];
__device__ __nv_bfloat16 g_wprojH[(size_t)DD * KK];  // transposed [N,K]
__device__ __nv_bfloat16 g_wprojL[(size_t)DD * KK];

// ---------------------------------------------------------------------------
// PTX helpers (sm_80+ only; harness targets sm_103 w/o 'a' — no tcgen05)
// ---------------------------------------------------------------------------
__device__ __forceinline__ uint32_t smem_to_u32(const void* p) {
    uint32_t a;
    asm("{ .reg .u64 t; cvta.to.shared.u64 t, %1; cvt.u32.u64 %0, t; }"
        : "=r"(a) : "l"(p));
    return a;
}
__device__ __forceinline__ void cp16(uint32_t dst, const void* src, uint32_t sz) {
    asm volatile("cp.async.ca.shared.global [%0], [%1], 16, %2;"
                 :: "r"(dst), "l"(src), "r"(sz) : "memory");
}
#define CP_COMMIT() asm volatile("cp.async.commit_group;" ::: "memory")
#define CP_WAIT(n)  asm volatile("cp.async.wait_group %0;" :: "n"(n) : "memory")

__device__ __forceinline__ void ldsm_x4(uint32_t* r, uint32_t addr) {
    asm volatile("ldmatrix.sync.aligned.m8n8.x4.shared.b16 {%0,%1,%2,%3}, [%4];"
                 : "=r"(r[0]), "=r"(r[1]), "=r"(r[2]), "=r"(r[3]) : "r"(addr));
}
__device__ __forceinline__ void ldsm_x2(uint32_t* r, uint32_t addr) {
    asm volatile("ldmatrix.sync.aligned.m8n8.x2.shared.b16 {%0,%1}, [%2];"
                 : "=r"(r[0]), "=r"(r[1]) : "r"(addr));
}
__device__ __forceinline__ void ldsm_x2t(uint32_t* r, uint32_t addr) {
    asm volatile("ldmatrix.sync.aligned.m8n8.x2.trans.shared.b16 {%0,%1}, [%2];"
                 : "=r"(r[0]), "=r"(r[1]) : "r"(addr));
}
__device__ __forceinline__ void mma16816(float* d, const uint32_t* a, const uint32_t* b) {
    asm volatile("mma.sync.aligned.m16n8k16.row.col.f32.bf16.bf16.f32 "
                 "{%0,%1,%2,%3}, {%4,%5,%6,%7}, {%8,%9}, {%0,%1,%2,%3};"
                 : "+f"(d[0]), "+f"(d[1]), "+f"(d[2]), "+f"(d[3])
                 : "r"(a[0]), "r"(a[1]), "r"(a[2]), "r"(a[3]), "r"(b[0]), "r"(b[1]));
}
__device__ __forceinline__ void split_pair(float a, float b, uint32_t& hi, uint32_t& lo) {
    __nv_bfloat16 ha = __float2bfloat16(a), hb = __float2bfloat16(b);
    float la = a - __bfloat162float(ha), lb = b - __bfloat162float(hb);
    __nv_bfloat16 hla = __float2bfloat16(la), hlb = __float2bfloat16(lb);
    hi = ((uint32_t)*(uint16_t*)&hb << 16) | *(uint16_t*)&ha;
    lo = ((uint32_t)*(uint16_t*)&hlb << 16) | *(uint16_t*)&hla;
}

// ---------------------------------------------------------------------------
// Split fp32 -> (hi, lo) bf16, same layout.
// ---------------------------------------------------------------------------
__global__ void split_kernel(const float4* __restrict__ in,
                             uint2* __restrict__ hi, uint2* __restrict__ lo, int n4)
{
    int i = blockIdx.x * blockDim.x + threadIdx.x;
    if (i >= n4) return;
    float4 v = in[i];
    uint2 ho, loo;
    split_pair(v.x, v.y, ho.x, loo.x);
    split_pair(v.z, v.w, ho.y, loo.y);
    hi[i] = ho;
    lo[i] = loo;
}

// ---------------------------------------------------------------------------
// Transpose + split: in fp32 [R, C] -> hi/lo bf16 [C, R]
// ---------------------------------------------------------------------------
__global__ void tsplit_kernel(const float* __restrict__ in,
                              __nv_bfloat16* __restrict__ hi,
                              __nv_bfloat16* __restrict__ lo, int R, int C)
{
    __shared__ float t[32][33];
    int c0 = blockIdx.x * 32, r0 = blockIdx.y * 32;
    int tx = threadIdx.x, ty = threadIdx.y;
#pragma unroll
    for (int i = ty; i < 32; i += 8)
        t[i][tx] = in[(size_t)(r0 + i) * C + c0 + tx];
    __syncthreads();
#pragma unroll
    for (int i = ty; i < 32; i += 8) {
        float x = t[tx][i];
        __nv_bfloat16 h = __float2bfloat16(x);
        __nv_bfloat16 l = __float2bfloat16(x - __bfloat162float(h));
        size_t off = (size_t)(c0 + i) * R + r0 + tx;
        hi[off] = h;
        lo[off] = l;
    }
}

// ---------------------------------------------------------------------------
// bf16x3-split MMA GEMM: C[M,N] = A[M,K] @ B[N,K]^T + bias[N]
// MODE 0: fp32 C out.  MODE 1: bf16 hi/lo out, cols<DD scaled by SCALE_F.
// 2 CTAs/SM (launch_bounds 256,2; smem 96KB x2 fits 228KB).
// Frag loads staged (ah,bh -> hh; bl -> hl; al -> lh) to cap live regs;
// B fragments via ldmatrix.x4 (half the LDSM count).
// ---------------------------------------------------------------------------
#define BK      32
#define STAGES  3
#define TBYTES  8192
#define STAGE_BYTES (4 * TBYTES)
#define NCH     (KK / BK)

__device__ __forceinline__ uint32_t swz(int r, int c) {
    return (uint32_t)(r * 64 + ((c ^ ((r >> 1) & 3)) << 4));
}

template<int MODE>
__global__ __launch_bounds__(256, 2) void gemm_mma_kernel(
    const __nv_bfloat16* __restrict__ Ahi, const __nv_bfloat16* __restrict__ Alo,
    const __nv_bfloat16* __restrict__ Bhi, const __nv_bfloat16* __restrict__ Blo,
    const float* __restrict__ bias, float* __restrict__ C,
    __nv_bfloat16* __restrict__ CH, __nv_bfloat16* __restrict__ CL,
    int M, int N)
{
    extern __shared__ char smem[];
    const uint32_t sbase = smem_to_u32(smem);

    const int tid = threadIdx.x;
    const int lane = tid & 31;
    const int wid = tid >> 5;
    const int wm = wid & 3;
    const int wn = wid >> 2;
    const int m0 = blockIdx.y * 128;
    const int n0 = blockIdx.x * 128;

    auto load_stage = [&](int kt, int slot) {
        const int k0 = kt * BK;
        const uint32_t st = sbase + slot * STAGE_BYTES;
#pragma unroll
        for (int i = 0; i < 8; ++i) {
            int idx = tid + i * 256;
            int tile = idx >> 9;
            int rem = idx & 511;
            int r = rem >> 2;
            int c = rem & 3;
            uint32_t dst = st + tile * TBYTES + swz(r, c);
            const __nv_bfloat16* gp;
            uint32_t sz = 16;
            if (tile < 2) {
                int m = m0 + r;
                int mc = m < M ? m : 0;
                if (m >= M) sz = 0;
                gp = (tile == 0 ? Ahi : Alo) + (size_t)mc * KK + k0 + c * 8;
            } else {
                int n = n0 + r;
                gp = (tile == 2 ? Bhi : Blo) + (size_t)n * KK + k0 + c * 8;
            }
            cp16(dst, gp, sz);
        }
        CP_COMMIT();
    };

    float acc[2][8][4];
#pragma unroll
    for (int t = 0; t < 2; ++t)
#pragma unroll
        for (int j = 0; j < 8; ++j)
#pragma unroll
            for (int v = 0; v < 4; ++v) acc[t][j][v] = 0.f;

    load_stage(0, 0);
    load_stage(1, 1);

    // fragment addresses (constant across kt up to stage base)
    // A rows for ldsm_x4: r covers 16 rows via lane&15, col half via lane>>4
    const int ar[2] = { wm * 32 + (lane & 15), wm * 32 + 16 + (lane & 15) };
    const int acl = (lane >> 4);              // 0/1 within k16
    // B rows for ldsm_x4: 16 n-rows per jj, plus matrix pair selection
    const int br = wn * 64 + (lane & 7) + ((lane >> 4) & 1) * 8;
    const int bcl = (lane >> 3) & 1;

    for (int kt = 0; kt < NCH; ++kt) {
        CP_WAIT(1);
        __syncthreads();
        if (kt + 2 < NCH) load_stage(kt + 2, (kt + 2) % STAGES);

        const uint32_t st = sbase + (kt % STAGES) * STAGE_BYTES;
#pragma unroll
        for (int ks = 0; ks < 2; ++ks) {
            uint32_t a[2][4], b0[4][4], b1[4][4];
            // -- load A-hi, B-hi --
#pragma unroll
            for (int t = 0; t < 2; ++t)
                ldsm_x4(a[t], st + 0 * TBYTES + swz(ar[t], ks * 2 + acl));
#pragma unroll
            for (int jj = 0; jj < 4; ++jj)
                ldsm_x4(b0[jj], st + 2 * TBYTES + swz(br + jj * 16, ks * 2 + bcl));
            // -- term hh --
#pragma unroll
            for (int t = 0; t < 2; ++t)
#pragma unroll
                for (int jj = 0; jj < 4; ++jj) {
                    mma16816(acc[t][jj * 2 + 0], a[t], &b0[jj][0]);
                    mma16816(acc[t][jj * 2 + 1], a[t], &b0[jj][2]);
                }
            // -- load B-lo, term hl --
#pragma unroll
            for (int jj = 0; jj < 4; ++jj)
                ldsm_x4(b1[jj], st + 3 * TBYTES + swz(br + jj * 16, ks * 2 + bcl));
#pragma unroll
            for (int t = 0; t < 2; ++t)
#pragma unroll
                for (int jj = 0; jj < 4; ++jj) {
                    mma16816(acc[t][jj * 2 + 0], a[t], &b1[jj][0]);
                    mma16816(acc[t][jj * 2 + 1], a[t], &b1[jj][2]);
                }
            // -- load A-lo (reuse a), term lh --
#pragma unroll
            for (int t = 0; t < 2; ++t)
                ldsm_x4(a[t], st + 1 * TBYTES + swz(ar[t], ks * 2 + acl));
#pragma unroll
            for (int t = 0; t < 2; ++t)
#pragma unroll
                for (int jj = 0; jj < 4; ++jj) {
                    mma16816(acc[t][jj * 2 + 0], a[t], &b0[jj][0]);
                    mma16816(acc[t][jj * 2 + 1], a[t], &b0[jj][2]);
                }
        }
    }

    const int rb = m0 + wm * 32 + (lane >> 2);
    const int cb = n0 + wn * 64 + (lane & 3) * 2;
#pragma unroll
    for (int t = 0; t < 2; ++t) {
        int r0 = rb + t * 16;
#pragma unroll
        for (int j = 0; j < 8; ++j) {
            int col = cb + j * 8;
            float2 b2 = *(const float2*)&bias[col];
            if constexpr (MODE == 0) {
                if (r0 < M) {
                    float2 o = {acc[t][j][0] + b2.x, acc[t][j][1] + b2.y};
                    *(float2*)&C[(size_t)r0 * N + col] = o;
                }
                if (r0 + 8 < M) {
                    float2 o = {acc[t][j][2] + b2.x, acc[t][j][3] + b2.y};
                    *(float2*)&C[(size_t)(r0 + 8) * N + col] = o;
                }
            } else {
                float s = (col < DD) ? SCALE_F : 1.0f;
                if (r0 < M) {
                    uint32_t hi, lo;
                    split_pair((acc[t][j][0] + b2.x) * s, (acc[t][j][1] + b2.y) * s, hi, lo);
                    *(uint32_t*)&CH[(size_t)r0 * N + col] = hi;
                    *(uint32_t*)&CL[(size_t)r0 * N + col] = lo;
                }
                if (r0 + 8 < M) {
                    uint32_t hi, lo;
                    split_pair((acc[t][j][2] + b2.x) * s, (acc[t][j][3] + b2.y) * s, hi, lo);
                    *(uint32_t*)&CH[(size_t)(r0 + 8) * N + col] = hi;
                    *(uint32_t*)&CL[(size_t)(r0 + 8) * N + col] = lo;
                }
            }
        }
    }
}

// ---------------------------------------------------------------------------
// Tensor-core flash attention (unchanged from R5 - passing).
// ---------------------------------------------------------------------------
#define SM_QH   0
#define SM_QL   24576
#define SM_KV   49152
#define SM_PH   147456
#define SM_PL   163840
#define SM_STAT 180224
#define SM_ATT_TOTAL 182272

__device__ __forceinline__ uint32_t swzQ(int r, int c) {
    return (uint32_t)(r * 192 + ((c ^ ((r >> 1) & 3)) << 4));
}
__device__ __forceinline__ uint32_t swzP(int r, int c) {
    return (uint32_t)(r * 128 + ((c ^ (r & 7)) << 4));
}

__global__ __launch_bounds__(256, 1) void attn_tc_kernel(
    const __nv_bfloat16* __restrict__ qkvH, const __nv_bfloat16* __restrict__ qkvL,
    __nv_bfloat16* __restrict__ attH, __nv_bfloat16* __restrict__ attL)
{
    extern __shared__ char smem[];
    const uint32_t sb = smem_to_u32(smem);
    const int tid = threadIdx.x;
    const int lane = tid & 31;
    const int wid = tid >> 5;
    const int wm = wid & 3;
    const int wn = wid >> 2;
    const int b = blockIdx.z;
    const int h = blockIdx.y;
    const int q0 = blockIdx.x * 128;

    float* sMax = (float*)(smem + SM_STAT);
    float* sSum = (float*)(smem + SM_STAT + 1024);

    const size_t rowbase = (size_t)b * SS * N1 + (size_t)h * HD;

    {
        int r = tid >> 1;
        int cbase = (tid & 1) * 6;
        int s = q0 + r;
        int sc_ = s < SS ? s : SS - 1;
        const __nv_bfloat16* srcH = qkvH + rowbase + (size_t)sc_ * N1;
        const __nv_bfloat16* srcL = qkvL + rowbase + (size_t)sc_ * N1;
#pragma unroll
        for (int cc = 0; cc < 6; ++cc) {
            int c = cbase + cc;
            int ca = c < 11 ? c : 10;
            uint32_t sz = (c < 11 && s < SS) ? 16 : 0;
            cp16(sb + SM_QH + swzQ(r, c), srcH + ca * 8, sz);
            cp16(sb + SM_QL + swzQ(r, c), srcL + ca * 8, sz);
        }
    }

    auto load_kv = [&](int kt, int buf) {
        int r = tid >> 2;
        int cbase = (tid & 3) * 3;
        int s = kt * 64 + r;
        int sc_ = s < SS ? s : SS - 1;
        const uint32_t kb = sb + SM_KV + buf * 49152;
        const __nv_bfloat16* base[4] = {
            qkvH + rowbase + (size_t)sc_ * N1 + DD,
            qkvL + rowbase + (size_t)sc_ * N1 + DD,
            qkvH + rowbase + (size_t)sc_ * N1 + 2 * DD,
            qkvL + rowbase + (size_t)sc_ * N1 + 2 * DD
        };
#pragma unroll
        for (int arr = 0; arr < 4; ++arr) {
#pragma unroll
            for (int cc = 0; cc < 3; ++cc) {
                int c = cbase + cc;
                int ca = c < 11 ? c : 10;
                uint32_t sz = (c < 11 && s < SS) ? 16 : 0;
                cp16(kb + arr * 12288 + swzQ(r, c), base[arr] + ca * 8, sz);
            }
        }
    };

    load_kv(0, 0);
    CP_COMMIT();

    float acc[2][6][4];
#pragma unroll
    for (int ti = 0; ti < 2; ++ti)
#pragma unroll
        for (int j = 0; j < 6; ++j)
#pragma unroll
            for (int v = 0; v < 4; ++v) acc[ti][j][v] = 0.f;
    float m_old[2][2] = {{-1e30f, -1e30f}, {-1e30f, -1e30f}};
    float l_run[2][2] = {{0.f, 0.f}, {0.f, 0.f}};

    const int NKT = (SS + 63) / 64;

    for (int kt = 0; kt < NKT; ++kt) {
        CP_WAIT(0);
        __syncthreads();
        if (kt + 1 < NKT) load_kv(kt + 1, (kt + 1) & 1);
        CP_COMMIT();

        const uint32_t kb = sb + SM_KV + (kt & 1) * 49152;

        // ---- QK^T ----
        float sc[2][4][4];
#pragma unroll
        for (int ti = 0; ti < 2; ++ti)
#pragma unroll
            for (int j = 0; j < 4; ++j)
#pragma unroll
                for (int v = 0; v < 4; ++v) sc[ti][j][v] = 0.f;

#pragma unroll
        for (int ks = 0; ks < 6; ++ks) {
            uint32_t ah[2][4], al[2][4], bh[4][2], bl[4][2];
#pragma unroll
            for (int ti = 0; ti < 2; ++ti) {
                int r = wm * 32 + ti * 16 + (lane & 15);
                int c = ks * 2 + (lane >> 4);
                uint32_t off = swzQ(r, c);
                ldsm_x4(ah[ti], sb + SM_QH + off);
                ldsm_x4(al[ti], sb + SM_QL + off);
            }
#pragma unroll
            for (int j = 0; j < 4; ++j) {
                int r = wn * 32 + j * 8 + (lane & 7);
                int c = ks * 2 + ((lane >> 3) & 1);
                uint32_t off = swzQ(r, c);
                ldsm_x2(bh[j], kb + 0 + off);
                ldsm_x2(bl[j], kb + 12288 + off);
            }
#pragma unroll
            for (int ti = 0; ti < 2; ++ti)
#pragma unroll
                for (int j = 0; j < 4; ++j)
                    mma16816(sc[ti][j], ah[ti], bh[j]);
#pragma unroll
            for (int ti = 0; ti < 2; ++ti)
#pragma unroll
                for (int j = 0; j < 4; ++j)
                    mma16816(sc[ti][j], ah[ti], bl[j]);
#pragma unroll
            for (int ti = 0; ti < 2; ++ti)
#pragma unroll
                for (int j = 0; j < 4; ++j)
                    mma16816(sc[ti][j], al[ti], bh[j]);
        }

        // ---- mask ----
#pragma unroll
        for (int j = 0; j < 4; ++j) {
            int c0 = kt * 64 + wn * 32 + j * 8 + (lane & 3) * 2;
            if (c0 >= SS) { sc[0][j][0] = sc[0][j][2] = sc[1][j][0] = sc[1][j][2] = -1e30f; }
            if (c0 + 1 >= SS) { sc[0][j][1] = sc[0][j][3] = sc[1][j][1] = sc[1][j][3] = -1e30f; }
        }

        // ---- row max ----
#pragma unroll
        for (int ti = 0; ti < 2; ++ti)
#pragma unroll
            for (int hh = 0; hh < 2; ++hh) {
                float mt = -1e30f;
#pragma unroll
                for (int j = 0; j < 4; ++j)
                    mt = fmaxf(mt, fmaxf(sc[ti][j][hh * 2], sc[ti][j][hh * 2 + 1]));
                mt = fmaxf(mt, __shfl_xor_sync(0xffffffffu, mt, 1));
                mt = fmaxf(mt, __shfl_xor_sync(0xffffffffu, mt, 2));
                if ((lane & 3) == 0) {
                    int rl = wm * 32 + ti * 16 + hh * 8 + (lane >> 2);
                    sMax[wn * 128 + rl] = mt;
                }
            }
        __syncthreads();

        float mnew[2][2], corr[2][2];
#pragma unroll
        for (int ti = 0; ti < 2; ++ti)
#pragma unroll
            for (int hh = 0; hh < 2; ++hh) {
                int rl = wm * 32 + ti * 16 + hh * 8 + (lane >> 2);
                float m2 = fmaxf(sMax[rl], sMax[128 + rl]);
                float mn = fmaxf(m_old[ti][hh], m2);
                corr[ti][hh] = __expf(m_old[ti][hh] - mn);
                mnew[ti][hh] = mn;
                m_old[ti][hh] = mn;
            }

        // ---- exp, P store, sums ----
        float sum_[2][2] = {{0.f, 0.f}, {0.f, 0.f}};
#pragma unroll
        for (int ti = 0; ti < 2; ++ti) {
            int r0 = wm * 32 + ti * 16 + (lane >> 2);
#pragma unroll
            for (int j = 0; j < 4; ++j) {
                float p0 = __expf(sc[ti][j][0] - mnew[ti][0]);
                float p1 = __expf(sc[ti][j][1] - mnew[ti][0]);
                float p2 = __expf(sc[ti][j][2] - mnew[ti][1]);
                float p3 = __expf(sc[ti][j][3] - mnew[ti][1]);
                sum_[ti][0] += p0 + p1;
                sum_[ti][1] += p2 + p3;
                int colc = wn * 32 + j * 8 + (lane & 3) * 2;
                uint32_t o0 = swzP(r0, colc >> 3) + (colc & 7) * 2;
                uint32_t o1 = swzP(r0 + 8, colc >> 3) + (colc & 7) * 2;
                uint32_t hi, lo;
                split_pair(p0, p1, hi, lo);
                *(uint32_t*)(smem + SM_PH + o0) = hi;
                *(uint32_t*)(smem + SM_PL + o0) = lo;
                split_pair(p2, p3, hi, lo);
                *(uint32_t*)(smem + SM_PH + o1) = hi;
                *(uint32_t*)(smem + SM_PL + o1) = lo;
            }
        }
#pragma unroll
        for (int ti = 0; ti < 2; ++ti)
#pragma unroll
            for (int hh = 0; hh < 2; ++hh) {
                float s = sum_[ti][hh];
                s += __shfl_xor_sync(0xffffffffu, s, 1);
                s += __shfl_xor_sync(0xffffffffu, s, 2);
                if ((lane & 3) == 0) {
                    int rl = wm * 32 + ti * 16 + hh * 8 + (lane >> 2);
                    sSum[wn * 128 + rl] = s;
                }
            }
#pragma unroll
        for (int ti = 0; ti < 2; ++ti)
#pragma unroll
            for (int j = 0; j < 6; ++j) {
                acc[ti][j][0] *= corr[ti][0];
                acc[ti][j][1] *= corr[ti][0];
                acc[ti][j][2] *= corr[ti][1];
                acc[ti][j][3] *= corr[ti][1];
            }
        __syncthreads();
#pragma unroll
        for (int ti = 0; ti < 2; ++ti)
#pragma unroll
            for (int hh = 0; hh < 2; ++hh) {
                int rl = wm * 32 + ti * 16 + hh * 8 + (lane >> 2);
                l_run[ti][hh] = l_run[ti][hh] * corr[ti][hh] + sSum[rl] + sSum[128 + rl];
            }

        // ---- P.V ----
#pragma unroll
        for (int ks = 0; ks < 4; ++ks) {
            uint32_t ph[2][4], pl[2][4], vh[6][2], vl[6][2];
#pragma unroll
            for (int ti = 0; ti < 2; ++ti) {
                int r = wm * 32 + ti * 16 + (lane & 15);
                int c = ks * 2 + (lane >> 4);
                uint32_t off = swzP(r, c);
                ldsm_x4(ph[ti], sb + SM_PH + off);
                ldsm_x4(pl[ti], sb + SM_PL + off);
            }
#pragma unroll
            for (int j = 0; j < 6; ++j) {
                int rk = ks * 16 + (lane & 15);
                int c = wn * 6 + j;
                uint32_t off = swzQ(rk, c);
                ldsm_x2t(vh[j], kb + 24576 + off);
                ldsm_x2t(vl[j], kb + 36864 + off);
            }
#pragma unroll
            for (int ti = 0; ti < 2; ++ti)
#pragma unroll
                for (int j = 0; j < 6; ++j)
                    mma16816(acc[ti][j], ph[ti], vh[j]);
#pragma unroll
            for (int ti = 0; ti < 2; ++ti)
#pragma unroll
                for (int j = 0; j < 6; ++j)
                    mma16816(acc[ti][j], ph[ti], vl[j]);
#pragma unroll
            for (int ti = 0; ti < 2; ++ti)
#pragma unroll
                for (int j = 0; j < 6; ++j)
                    mma16816(acc[ti][j], pl[ti], vh[j]);
        }
    }

    // ---- epilogue ----
    float inv[2][2];
#pragma unroll
    for (int ti = 0; ti < 2; ++ti)
#pragma unroll
        for (int hh = 0; hh < 2; ++hh)
            inv[ti][hh] = 1.f / l_run[ti][hh];

#pragma unroll
    for (int ti = 0; ti < 2; ++ti)
#pragma unroll
        for (int j = 0; j < 6; ++j) {
            int col = wn * 48 + j * 8 + (lane & 3) * 2;
            if (col >= HD) continue;
#pragma unroll
            for (int hh = 0; hh < 2; ++hh) {
                int s = q0 + wm * 32 + ti * 16 + hh * 8 + (lane >> 2);
                if (s >= SS) continue;
                float o0 = acc[ti][j][hh * 2] * inv[ti][hh];
                float o1 = acc[ti][j][hh * 2 + 1] * inv[ti][hh];
                uint32_t hi, lo;
                split_pair(o0, o1, hi, lo);
                size_t off = (size_t)(b * SS + s) * KK + (size_t)h * HD + col;
                *(uint32_t*)&attH[off] = hi;
                *(uint32_t*)&attL[off] = lo;
            }
        }
}

// ---------------------------------------------------------------------------
extern "C" void kernel_launch(void* const* d_in, const int* in_sizes, int n_in,
                              void* d_out, int out_size)
{
    const float* hs     = (const float*)d_in[0];
    const float* w_qkv  = (const float*)d_in[1];
    const float* b_qkv  = (const float*)d_in[2];
    const float* w_proj = (const float*)d_in[3];
    const float* b_proj = (const float*)d_in[4];
    float* out = (float*)d_out;

    __nv_bfloat16 *hsH, *hsL, *qkvH, *qkvL, *attH, *attL, *wqH, *wqL, *wpH, *wpL;
    cudaGetSymbolAddress((void**)&hsH, g_hsH);
    cudaGetSymbolAddress((void**)&hsL, g_hsL);
    cudaGetSymbolAddress((void**)&qkvH, g_qkvH);
    cudaGetSymbolAddress((void**)&qkvL, g_qkvL);
    cudaGetSymbolAddress((void**)&attH, g_attH);
    cudaGetSymbolAddress((void**)&attL, g_attL);
    cudaGetSymbolAddress((void**)&wqH, g_wqkvH);
    cudaGetSymbolAddress((void**)&wqL, g_wqkvL);
    cudaGetSymbolAddress((void**)&wpH, g_wprojH);
    cudaGetSymbolAddress((void**)&wpL, g_wprojL);

    const int gemm_smem = STAGES * STAGE_BYTES;   // 96 KB
    cudaFuncSetAttribute(gemm_mma_kernel<0>, cudaFuncAttributeMaxDynamicSharedMemorySize, gemm_smem);
    cudaFuncSetAttribute(gemm_mma_kernel<1>, cudaFuncAttributeMaxDynamicSharedMemorySize, gemm_smem);
    cudaFuncSetAttribute(attn_tc_kernel, cudaFuncAttributeMaxDynamicSharedMemorySize, SM_ATT_TOTAL);

    // 0a) split hidden_states
    {
        int n4 = MM * KK / 4;
        split_kernel<<<(n4 + 255) / 256, 256>>>((const float4*)hs, (uint2*)hsH, (uint2*)hsL, n4);
    }
    // 0b) transpose+split weights
    {
        dim3 g(N1 / 32, KK / 32);
        tsplit_kernel<<<g, dim3(32, 8)>>>(w_qkv, wqH, wqL, KK, N1);
    }
    {
        dim3 g(DD / 32, KK / 32);
        tsplit_kernel<<<g, dim3(32, 8)>>>(w_proj, wpH, wpL, KK, DD);
    }
    // 1) QKV projection -> bf16 hi/lo (q pre-scaled)
    {
        dim3 g(N1 / 128, (MM + 127) / 128);
        gemm_mma_kernel<1><<<g, 256, gemm_smem>>>(hsH, hsL, wqH, wqL, b_qkv,
                                                  nullptr, qkvH, qkvL, MM, N1);
    }
    // 2) tensor-core flash attention -> bf16 hi/lo
    {
        dim3 g((SS + 127) / 128, HH, BB);
        attn_tc_kernel<<<g, 256, SM_ATT_TOTAL>>>(qkvH, qkvL, attH, attL);
    }
    // 3) output projection -> fp32
    {
        dim3 g(DD / 128, (MM + 127) / 128);
        gemm_mma_kernel<0><<<g, 256, gemm_smem>>>(attH, attL, wpH, wpL, b_proj,
                                                  out, nullptr, nullptr, MM, DD);
    }
}

// round 7
// speedup vs baseline: 1.0390x; 1.0086x over previous
#include <cuda_runtime.h>
#include <cuda_bf16.h>
#include <cstdint>

// Problem constants
#define BB   16
#define SS   577
#define DD   1408
#define HH   16
#define HD   88
#define SCALE_F 0.10660035817780521f  // 1/sqrt(88)

#define MM   (BB * SS)      // 9232
#define N1   (3 * DD)       // 4224
#define KK   DD             // 1408

// ---------------------------------------------------------------------------
// Device-global scratch
// ---------------------------------------------------------------------------
__device__ __nv_bfloat16 g_hsH[(size_t)MM * KK];
__device__ __nv_bfloat16 g_hsL[(size_t)MM * KK];
__device__ __nv_bfloat16 g_qkvH[(size_t)MM * N1];
__device__ __nv_bfloat16 g_qkvL[(size_t)MM * N1];
__device__ __nv_bfloat16 g_attH[(size_t)MM * KK];
__device__ __nv_bfloat16 g_attL[(size_t)MM * KK];
__device__ __nv_bfloat16 g_wqkvH[(size_t)N1 * KK];   // transposed [N,K]
__device__ __nv_bfloat16 g_wqkvL[(size_t)N1 * KK];
__device__ __nv_bfloat16 g_wprojH[(size_t)DD * KK];  // transposed [N,K]
__device__ __nv_bfloat16 g_wprojL[(size_t)DD * KK];

// ---------------------------------------------------------------------------
// PTX helpers (sm_80+ only; harness targets sm_103 w/o 'a' — no tcgen05)
// ---------------------------------------------------------------------------
__device__ __forceinline__ uint32_t smem_to_u32(const void* p) {
    uint32_t a;
    asm("{ .reg .u64 t; cvta.to.shared.u64 t, %1; cvt.u32.u64 %0, t; }"
        : "=r"(a) : "l"(p));
    return a;
}
__device__ __forceinline__ void cp16(uint32_t dst, const void* src, uint32_t sz) {
    asm volatile("cp.async.ca.shared.global [%0], [%1], 16, %2;"
                 :: "r"(dst), "l"(src), "r"(sz) : "memory");
}
#define CP_COMMIT() asm volatile("cp.async.commit_group;" ::: "memory")
#define CP_WAIT(n)  asm volatile("cp.async.wait_group %0;" :: "n"(n) : "memory")

__device__ __forceinline__ void ldsm_x4(uint32_t* r, uint32_t addr) {
    asm volatile("ldmatrix.sync.aligned.m8n8.x4.shared.b16 {%0,%1,%2,%3}, [%4];"
                 : "=r"(r[0]), "=r"(r[1]), "=r"(r[2]), "=r"(r[3]) : "r"(addr));
}
__device__ __forceinline__ void ldsm_x2(uint32_t* r, uint32_t addr) {
    asm volatile("ldmatrix.sync.aligned.m8n8.x2.shared.b16 {%0,%1}, [%2];"
                 : "=r"(r[0]), "=r"(r[1]) : "r"(addr));
}
__device__ __forceinline__ void ldsm_x2t(uint32_t* r, uint32_t addr) {
    asm volatile("ldmatrix.sync.aligned.m8n8.x2.trans.shared.b16 {%0,%1}, [%2];"
                 : "=r"(r[0]), "=r"(r[1]) : "r"(addr));
}
__device__ __forceinline__ void mma16816(float* d, const uint32_t* a, const uint32_t* b) {
    asm volatile("mma.sync.aligned.m16n8k16.row.col.f32.bf16.bf16.f32 "
                 "{%0,%1,%2,%3}, {%4,%5,%6,%7}, {%8,%9}, {%0,%1,%2,%3};"
                 : "+f"(d[0]), "+f"(d[1]), "+f"(d[2]), "+f"(d[3])
                 : "r"(a[0]), "r"(a[1]), "r"(a[2]), "r"(a[3]), "r"(b[0]), "r"(b[1]));
}
__device__ __forceinline__ void split_pair(float a, float b, uint32_t& hi, uint32_t& lo) {
    __nv_bfloat16 ha = __float2bfloat16(a), hb = __float2bfloat16(b);
    float la = a - __bfloat162float(ha), lb = b - __bfloat162float(hb);
    __nv_bfloat16 hla = __float2bfloat16(la), hlb = __float2bfloat16(lb);
    hi = ((uint32_t)*(uint16_t*)&hb << 16) | *(uint16_t*)&ha;
    lo = ((uint32_t)*(uint16_t*)&hlb << 16) | *(uint16_t*)&hla;
}

// ---------------------------------------------------------------------------
// Split fp32 -> (hi, lo) bf16, same layout.
// ---------------------------------------------------------------------------
__global__ void split_kernel(const float4* __restrict__ in,
                             uint2* __restrict__ hi, uint2* __restrict__ lo, int n4)
{
    int i = blockIdx.x * blockDim.x + threadIdx.x;
    if (i >= n4) return;
    float4 v = in[i];
    uint2 ho, loo;
    split_pair(v.x, v.y, ho.x, loo.x);
    split_pair(v.z, v.w, ho.y, loo.y);
    hi[i] = ho;
    lo[i] = loo;
}

// ---------------------------------------------------------------------------
// Transpose + split: in fp32 [R, C] -> hi/lo bf16 [C, R]
// ---------------------------------------------------------------------------
__global__ void tsplit_kernel(const float* __restrict__ in,
                              __nv_bfloat16* __restrict__ hi,
                              __nv_bfloat16* __restrict__ lo, int R, int C)
{
    __shared__ float t[32][33];
    int c0 = blockIdx.x * 32, r0 = blockIdx.y * 32;
    int tx = threadIdx.x, ty = threadIdx.y;
#pragma unroll
    for (int i = ty; i < 32; i += 8)
        t[i][tx] = in[(size_t)(r0 + i) * C + c0 + tx];
    __syncthreads();
#pragma unroll
    for (int i = ty; i < 32; i += 8) {
        float x = t[tx][i];
        __nv_bfloat16 h = __float2bfloat16(x);
        __nv_bfloat16 l = __float2bfloat16(x - __bfloat162float(h));
        size_t off = (size_t)(c0 + i) * R + r0 + tx;
        hi[off] = h;
        lo[off] = l;
    }
}

// ---------------------------------------------------------------------------
// bf16x3-split MMA GEMM: C[M,N] = A[M,K] @ B[N,K]^T + bias[N]
// CTA tile 256x128, warp tile 64x64 (8 warps = 4M x 2N), BK=32, 3 stages
// (144KB smem, 1 CTA/SM). LDSM/MMA wavefront ratio 0.67 (was 1.0).
// MODE 0: fp32 C out.  MODE 1: bf16 hi/lo out, cols<DD scaled by SCALE_F.
// ---------------------------------------------------------------------------
#define BK      32
#define STAGES  3
#define SM_AH   0
#define SM_AL   16384
#define SM_BH   32768
#define SM_BL   40960
#define STAGE_BYTES 49152
#define NCH     (KK / BK)

__device__ __forceinline__ uint32_t swz(int r, int c) {
    return (uint32_t)(r * 64 + ((c ^ ((r >> 1) & 3)) << 4));
}

template<int MODE>
__global__ __launch_bounds__(256, 1) void gemm_mma_kernel(
    const __nv_bfloat16* __restrict__ Ahi, const __nv_bfloat16* __restrict__ Alo,
    const __nv_bfloat16* __restrict__ Bhi, const __nv_bfloat16* __restrict__ Blo,
    const float* __restrict__ bias, float* __restrict__ C,
    __nv_bfloat16* __restrict__ CH, __nv_bfloat16* __restrict__ CL,
    int M, int N)
{
    extern __shared__ char smem[];
    const uint32_t sbase = smem_to_u32(smem);

    const int tid = threadIdx.x;
    const int lane = tid & 31;
    const int wid = tid >> 5;
    const int wm = wid & 3;          // 4 warps along M (64 rows each)
    const int wn = wid >> 2;         // 2 warps along N (64 cols each)
    const int m0 = blockIdx.y * 256;
    const int n0 = blockIdx.x * 128;

    // stage loader: 3072 16B-chunks, 12 per thread
    auto load_stage = [&](int kt, int slot) {
        const int k0 = kt * BK;
        const uint32_t st = sbase + slot * STAGE_BYTES;
#pragma unroll
        for (int i = 0; i < 12; ++i) {
            int idx = tid + i * 256;
            const __nv_bfloat16* gp;
            uint32_t dst;
            uint32_t sz = 16;
            if (idx < 2048) {                    // A region: 2 tiles x 1024
                int tile = idx >> 10;
                int rem = idx & 1023;
                int r = rem >> 2;
                int c = rem & 3;
                int m = m0 + r;
                int mc = m < M ? m : 0;
                if (m >= M) sz = 0;
                gp = (tile == 0 ? Ahi : Alo) + (size_t)mc * KK + k0 + c * 8;
                dst = st + tile * 16384 + swz(r, c);
            } else {                             // B region: 2 tiles x 512
                int idx2 = idx - 2048;
                int tile = idx2 >> 9;
                int rem = idx2 & 511;
                int r = rem >> 2;
                int c = rem & 3;
                int n = n0 + r;                  // N multiple of 128
                gp = (tile == 0 ? Bhi : Blo) + (size_t)n * KK + k0 + c * 8;
                dst = st + SM_BH + tile * 8192 + swz(r, c);
            }
            cp16(dst, gp, sz);
        }
        CP_COMMIT();
    };

    float acc[4][8][4];
#pragma unroll
    for (int t = 0; t < 4; ++t)
#pragma unroll
        for (int j = 0; j < 8; ++j)
#pragma unroll
            for (int v = 0; v < 4; ++v) acc[t][j][v] = 0.f;

    load_stage(0, 0);
    load_stage(1, 1);

    const int arow = wm * 64 + (lane & 15);
    const int acl = lane >> 4;
    const int brow = wn * 64 + (lane & 7) + ((lane >> 4) & 1) * 8;
    const int bcl = (lane >> 3) & 1;

    for (int kt = 0; kt < NCH; ++kt) {
        CP_WAIT(1);
        __syncthreads();
        if (kt + 2 < NCH) load_stage(kt + 2, (kt + 2) % STAGES);

        const uint32_t st = sbase + (kt % STAGES) * STAGE_BYTES;
#pragma unroll
        for (int ks = 0; ks < 2; ++ks) {
            uint32_t a[4][4], b0[4][4], b1[4][4];
            // A-hi + B-hi
#pragma unroll
            for (int t = 0; t < 4; ++t)
                ldsm_x4(a[t], st + SM_AH + swz(arow + t * 16, ks * 2 + acl));
#pragma unroll
            for (int jj = 0; jj < 4; ++jj)
                ldsm_x4(b0[jj], st + SM_BH + swz(brow + jj * 16, ks * 2 + bcl));
            // term hh
#pragma unroll
            for (int t = 0; t < 4; ++t)
#pragma unroll
                for (int jj = 0; jj < 4; ++jj) {
                    mma16816(acc[t][jj * 2 + 0], a[t], &b0[jj][0]);
                    mma16816(acc[t][jj * 2 + 1], a[t], &b0[jj][2]);
                }
            // B-lo, term hl
#pragma unroll
            for (int jj = 0; jj < 4; ++jj)
                ldsm_x4(b1[jj], st + SM_BL + swz(brow + jj * 16, ks * 2 + bcl));
#pragma unroll
            for (int t = 0; t < 4; ++t)
#pragma unroll
                for (int jj = 0; jj < 4; ++jj) {
                    mma16816(acc[t][jj * 2 + 0], a[t], &b1[jj][0]);
                    mma16816(acc[t][jj * 2 + 1], a[t], &b1[jj][2]);
                }
            // A-lo (reuse a), term lh
#pragma unroll
            for (int t = 0; t < 4; ++t)
                ldsm_x4(a[t], st + SM_AL + swz(arow + t * 16, ks * 2 + acl));
#pragma unroll
            for (int t = 0; t < 4; ++t)
#pragma unroll
                for (int jj = 0; jj < 4; ++jj) {
                    mma16816(acc[t][jj * 2 + 0], a[t], &b0[jj][0]);
                    mma16816(acc[t][jj * 2 + 1], a[t], &b0[jj][2]);
                }
        }
    }

    const int rb = m0 + wm * 64 + (lane >> 2);
    const int cb = n0 + wn * 64 + (lane & 3) * 2;
#pragma unroll
    for (int t = 0; t < 4; ++t) {
        int r0 = rb + t * 16;
#pragma unroll
        for (int j = 0; j < 8; ++j) {
            int col = cb + j * 8;
            float2 b2 = *(const float2*)&bias[col];
            if constexpr (MODE == 0) {
                if (r0 < M) {
                    float2 o = {acc[t][j][0] + b2.x, acc[t][j][1] + b2.y};
                    *(float2*)&C[(size_t)r0 * N + col] = o;
                }
                if (r0 + 8 < M) {
                    float2 o = {acc[t][j][2] + b2.x, acc[t][j][3] + b2.y};
                    *(float2*)&C[(size_t)(r0 + 8) * N + col] = o;
                }
            } else {
                float s = (col < DD) ? SCALE_F : 1.0f;
                if (r0 < M) {
                    uint32_t hi, lo;
                    split_pair((acc[t][j][0] + b2.x) * s, (acc[t][j][1] + b2.y) * s, hi, lo);
                    *(uint32_t*)&CH[(size_t)r0 * N + col] = hi;
                    *(uint32_t*)&CL[(size_t)r0 * N + col] = lo;
                }
                if (r0 + 8 < M) {
                    uint32_t hi, lo;
                    split_pair((acc[t][j][2] + b2.x) * s, (acc[t][j][3] + b2.y) * s, hi, lo);
                    *(uint32_t*)&CH[(size_t)(r0 + 8) * N + col] = hi;
                    *(uint32_t*)&CL[(size_t)(r0 + 8) * N + col] = lo;
                }
            }
        }
    }
}

// ---------------------------------------------------------------------------
// Tensor-core flash attention (unchanged - passing).
// ---------------------------------------------------------------------------
#define SM_QH   0
#define SM_QL   24576
#define SM_KV   49152
#define SM_PH   147456
#define SM_PL   163840
#define SM_STAT 180224
#define SM_ATT_TOTAL 182272

__device__ __forceinline__ uint32_t swzQ(int r, int c) {
    return (uint32_t)(r * 192 + ((c ^ ((r >> 1) & 3)) << 4));
}
__device__ __forceinline__ uint32_t swzP(int r, int c) {
    return (uint32_t)(r * 128 + ((c ^ (r & 7)) << 4));
}

__global__ __launch_bounds__(256, 1) void attn_tc_kernel(
    const __nv_bfloat16* __restrict__ qkvH, const __nv_bfloat16* __restrict__ qkvL,
    __nv_bfloat16* __restrict__ attH, __nv_bfloat16* __restrict__ attL)
{
    extern __shared__ char smem[];
    const uint32_t sb = smem_to_u32(smem);
    const int tid = threadIdx.x;
    const int lane = tid & 31;
    const int wid = tid >> 5;
    const int wm = wid & 3;
    const int wn = wid >> 2;
    const int b = blockIdx.z;
    const int h = blockIdx.y;
    const int q0 = blockIdx.x * 128;

    float* sMax = (float*)(smem + SM_STAT);
    float* sSum = (float*)(smem + SM_STAT + 1024);

    const size_t rowbase = (size_t)b * SS * N1 + (size_t)h * HD;

    {
        int r = tid >> 1;
        int cbase = (tid & 1) * 6;
        int s = q0 + r;
        int sc_ = s < SS ? s : SS - 1;
        const __nv_bfloat16* srcH = qkvH + rowbase + (size_t)sc_ * N1;
        const __nv_bfloat16* srcL = qkvL + rowbase + (size_t)sc_ * N1;
#pragma unroll
        for (int cc = 0; cc < 6; ++cc) {
            int c = cbase + cc;
            int ca = c < 11 ? c : 10;
            uint32_t sz = (c < 11 && s < SS) ? 16 : 0;
            cp16(sb + SM_QH + swzQ(r, c), srcH + ca * 8, sz);
            cp16(sb + SM_QL + swzQ(r, c), srcL + ca * 8, sz);
        }
    }

    auto load_kv = [&](int kt, int buf) {
        int r = tid >> 2;
        int cbase = (tid & 3) * 3;
        int s = kt * 64 + r;
        int sc_ = s < SS ? s : SS - 1;
        const uint32_t kb = sb + SM_KV + buf * 49152;
        const __nv_bfloat16* base[4] = {
            qkvH + rowbase + (size_t)sc_ * N1 + DD,
            qkvL + rowbase + (size_t)sc_ * N1 + DD,
            qkvH + rowbase + (size_t)sc_ * N1 + 2 * DD,
            qkvL + rowbase + (size_t)sc_ * N1 + 2 * DD
        };
#pragma unroll
        for (int arr = 0; arr < 4; ++arr) {
#pragma unroll
            for (int cc = 0; cc < 3; ++cc) {
                int c = cbase + cc;
                int ca = c < 11 ? c : 10;
                uint32_t sz = (c < 11 && s < SS) ? 16 : 0;
                cp16(kb + arr * 12288 + swzQ(r, c), base[arr] + ca * 8, sz);
            }
        }
    };

    load_kv(0, 0);
    CP_COMMIT();

    float acc[2][6][4];
#pragma unroll
    for (int ti = 0; ti < 2; ++ti)
#pragma unroll
        for (int j = 0; j < 6; ++j)
#pragma unroll
            for (int v = 0; v < 4; ++v) acc[ti][j][v] = 0.f;
    float m_old[2][2] = {{-1e30f, -1e30f}, {-1e30f, -1e30f}};
    float l_run[2][2] = {{0.f, 0.f}, {0.f, 0.f}};

    const int NKT = (SS + 63) / 64;

    for (int kt = 0; kt < NKT; ++kt) {
        CP_WAIT(0);
        __syncthreads();
        if (kt + 1 < NKT) load_kv(kt + 1, (kt + 1) & 1);
        CP_COMMIT();

        const uint32_t kb = sb + SM_KV + (kt & 1) * 49152;

        // ---- QK^T ----
        float sc[2][4][4];
#pragma unroll
        for (int ti = 0; ti < 2; ++ti)
#pragma unroll
            for (int j = 0; j < 4; ++j)
#pragma unroll
                for (int v = 0; v < 4; ++v) sc[ti][j][v] = 0.f;

#pragma unroll
        for (int ks = 0; ks < 6; ++ks) {
            uint32_t ah[2][4], al[2][4], bh[4][2], bl[4][2];
#pragma unroll
            for (int ti = 0; ti < 2; ++ti) {
                int r = wm * 32 + ti * 16 + (lane & 15);
                int c = ks * 2 + (lane >> 4);
                uint32_t off = swzQ(r, c);
                ldsm_x4(ah[ti], sb + SM_QH + off);
                ldsm_x4(al[ti], sb + SM_QL + off);
            }
#pragma unroll
            for (int j = 0; j < 4; ++j) {
                int r = wn * 32 + j * 8 + (lane & 7);
                int c = ks * 2 + ((lane >> 3) & 1);
                uint32_t off = swzQ(r, c);
                ldsm_x2(bh[j], kb + 0 + off);
                ldsm_x2(bl[j], kb + 12288 + off);
            }
#pragma unroll
            for (int ti = 0; ti < 2; ++ti)
#pragma unroll
                for (int j = 0; j < 4; ++j)
                    mma16816(sc[ti][j], ah[ti], bh[j]);
#pragma unroll
            for (int ti = 0; ti < 2; ++ti)
#pragma unroll
                for (int j = 0; j < 4; ++j)
                    mma16816(sc[ti][j], ah[ti], bl[j]);
#pragma unroll
            for (int ti = 0; ti < 2; ++ti)
#pragma unroll
                for (int j = 0; j < 4; ++j)
                    mma16816(sc[ti][j], al[ti], bh[j]);
        }

        // ---- mask ----
#pragma unroll
        for (int j = 0; j < 4; ++j) {
            int c0 = kt * 64 + wn * 32 + j * 8 + (lane & 3) * 2;
            if (c0 >= SS) { sc[0][j][0] = sc[0][j][2] = sc[1][j][0] = sc[1][j][2] = -1e30f; }
            if (c0 + 1 >= SS) { sc[0][j][1] = sc[0][j][3] = sc[1][j][1] = sc[1][j][3] = -1e30f; }
        }

        // ---- row max ----
#pragma unroll
        for (int ti = 0; ti < 2; ++ti)
#pragma unroll
            for (int hh = 0; hh < 2; ++hh) {
                float mt = -1e30f;
#pragma unroll
                for (int j = 0; j < 4; ++j)
                    mt = fmaxf(mt, fmaxf(sc[ti][j][hh * 2], sc[ti][j][hh * 2 + 1]));
                mt = fmaxf(mt, __shfl_xor_sync(0xffffffffu, mt, 1));
                mt = fmaxf(mt, __shfl_xor_sync(0xffffffffu, mt, 2));
                if ((lane & 3) == 0) {
                    int rl = wm * 32 + ti * 16 + hh * 8 + (lane >> 2);
                    sMax[wn * 128 + rl] = mt;
                }
            }
        __syncthreads();

        float mnew[2][2], corr[2][2];
#pragma unroll
        for (int ti = 0; ti < 2; ++ti)
#pragma unroll
            for (int hh = 0; hh < 2; ++hh) {
                int rl = wm * 32 + ti * 16 + hh * 8 + (lane >> 2);
                float m2 = fmaxf(sMax[rl], sMax[128 + rl]);
                float mn = fmaxf(m_old[ti][hh], m2);
                corr[ti][hh] = __expf(m_old[ti][hh] - mn);
                mnew[ti][hh] = mn;
                m_old[ti][hh] = mn;
            }

        // ---- exp, P store, sums ----
        float sum_[2][2] = {{0.f, 0.f}, {0.f, 0.f}};
#pragma unroll
        for (int ti = 0; ti < 2; ++ti) {
            int r0 = wm * 32 + ti * 16 + (lane >> 2);
#pragma unroll
            for (int j = 0; j < 4; ++j) {
                float p0 = __expf(sc[ti][j][0] - mnew[ti][0]);
                float p1 = __expf(sc[ti][j][1] - mnew[ti][0]);
                float p2 = __expf(sc[ti][j][2] - mnew[ti][1]);
                float p3 = __expf(sc[ti][j][3] - mnew[ti][1]);
                sum_[ti][0] += p0 + p1;
                sum_[ti][1] += p2 + p3;
                int colc = wn * 32 + j * 8 + (lane & 3) * 2;
                uint32_t o0 = swzP(r0, colc >> 3) + (colc & 7) * 2;
                uint32_t o1 = swzP(r0 + 8, colc >> 3) + (colc & 7) * 2;
                uint32_t hi, lo;
                split_pair(p0, p1, hi, lo);
                *(uint32_t*)(smem + SM_PH + o0) = hi;
                *(uint32_t*)(smem + SM_PL + o0) = lo;
                split_pair(p2, p3, hi, lo);
                *(uint32_t*)(smem + SM_PH + o1) = hi;
                *(uint32_t*)(smem + SM_PL + o1) = lo;
            }
        }
#pragma unroll
        for (int ti = 0; ti < 2; ++ti)
#pragma unroll
            for (int hh = 0; hh < 2; ++hh) {
                float s = sum_[ti][hh];
                s += __shfl_xor_sync(0xffffffffu, s, 1);
                s += __shfl_xor_sync(0xffffffffu, s, 2);
                if ((lane & 3) == 0) {
                    int rl = wm * 32 + ti * 16 + hh * 8 + (lane >> 2);
                    sSum[wn * 128 + rl] = s;
                }
            }
#pragma unroll
        for (int ti = 0; ti < 2; ++ti)
#pragma unroll
            for (int j = 0; j < 6; ++j) {
                acc[ti][j][0] *= corr[ti][0];
                acc[ti][j][1] *= corr[ti][0];
                acc[ti][j][2] *= corr[ti][1];
                acc[ti][j][3] *= corr[ti][1];
            }
        __syncthreads();
#pragma unroll
        for (int ti = 0; ti < 2; ++ti)
#pragma unroll
            for (int hh = 0; hh < 2; ++hh) {
                int rl = wm * 32 + ti * 16 + hh * 8 + (lane >> 2);
                l_run[ti][hh] = l_run[ti][hh] * corr[ti][hh] + sSum[rl] + sSum[128 + rl];
            }

        // ---- P.V ----
#pragma unroll
        for (int ks = 0; ks < 4; ++ks) {
            uint32_t ph[2][4], pl[2][4], vh[6][2], vl[6][2];
#pragma unroll
            for (int ti = 0; ti < 2; ++ti) {
                int r = wm * 32 + ti * 16 + (lane & 15);
                int c = ks * 2 + (lane >> 4);
                uint32_t off = swzP(r, c);
                ldsm_x4(ph[ti], sb + SM_PH + off);
                ldsm_x4(pl[ti], sb + SM_PL + off);
            }
#pragma unroll
            for (int j = 0; j < 6; ++j) {
                int rk = ks * 16 + (lane & 15);
                int c = wn * 6 + j;
                uint32_t off = swzQ(rk, c);
                ldsm_x2t(vh[j], kb + 24576 + off);
                ldsm_x2t(vl[j], kb + 36864 + off);
            }
#pragma unroll
            for (int ti = 0; ti < 2; ++ti)
#pragma unroll
                for (int j = 0; j < 6; ++j)
                    mma16816(acc[ti][j], ph[ti], vh[j]);
#pragma unroll
            for (int ti = 0; ti < 2; ++ti)
#pragma unroll
                for (int j = 0; j < 6; ++j)
                    mma16816(acc[ti][j], ph[ti], vl[j]);
#pragma unroll
            for (int ti = 0; ti < 2; ++ti)
#pragma unroll
                for (int j = 0; j < 6; ++j)
                    mma16816(acc[ti][j], pl[ti], vh[j]);
        }
    }

    // ---- epilogue ----
    float inv[2][2];
#pragma unroll
    for (int ti = 0; ti < 2; ++ti)
#pragma unroll
        for (int hh = 0; hh < 2; ++hh)
            inv[ti][hh] = 1.f / l_run[ti][hh];

#pragma unroll
    for (int ti = 0; ti < 2; ++ti)
#pragma unroll
        for (int j = 0; j < 6; ++j) {
            int col = wn * 48 + j * 8 + (lane & 3) * 2;
            if (col >= HD) continue;
#pragma unroll
            for (int hh = 0; hh < 2; ++hh) {
                int s = q0 + wm * 32 + ti * 16 + hh * 8 + (lane >> 2);
                if (s >= SS) continue;
                float o0 = acc[ti][j][hh * 2] * inv[ti][hh];
                float o1 = acc[ti][j][hh * 2 + 1] * inv[ti][hh];
                uint32_t hi, lo;
                split_pair(o0, o1, hi, lo);
                size_t off = (size_t)(b * SS + s) * KK + (size_t)h * HD + col;
                *(uint32_t*)&attH[off] = hi;
                *(uint32_t*)&attL[off] = lo;
            }
        }
}

// ---------------------------------------------------------------------------
extern "C" void kernel_launch(void* const* d_in, const int* in_sizes, int n_in,
                              void* d_out, int out_size)
{
    const float* hs     = (const float*)d_in[0];
    const float* w_qkv  = (const float*)d_in[1];
    const float* b_qkv  = (const float*)d_in[2];
    const float* w_proj = (const float*)d_in[3];
    const float* b_proj = (const float*)d_in[4];
    float* out = (float*)d_out;

    __nv_bfloat16 *hsH, *hsL, *qkvH, *qkvL, *attH, *attL, *wqH, *wqL, *wpH, *wpL;
    cudaGetSymbolAddress((void**)&hsH, g_hsH);
    cudaGetSymbolAddress((void**)&hsL, g_hsL);
    cudaGetSymbolAddress((void**)&qkvH, g_qkvH);
    cudaGetSymbolAddress((void**)&qkvL, g_qkvL);
    cudaGetSymbolAddress((void**)&attH, g_attH);
    cudaGetSymbolAddress((void**)&attL, g_attL);
    cudaGetSymbolAddress((void**)&wqH, g_wqkvH);
    cudaGetSymbolAddress((void**)&wqL, g_wqkvL);
    cudaGetSymbolAddress((void**)&wpH, g_wprojH);
    cudaGetSymbolAddress((void**)&wpL, g_wprojL);

    const int gemm_smem = STAGES * STAGE_BYTES;   // 144 KB
    cudaFuncSetAttribute(gemm_mma_kernel<0>, cudaFuncAttributeMaxDynamicSharedMemorySize, gemm_smem);
    cudaFuncSetAttribute(gemm_mma_kernel<1>, cudaFuncAttributeMaxDynamicSharedMemorySize, gemm_smem);
    cudaFuncSetAttribute(attn_tc_kernel, cudaFuncAttributeMaxDynamicSharedMemorySize, SM_ATT_TOTAL);

    // 0a) split hidden_states
    {
        int n4 = MM * KK / 4;
        split_kernel<<<(n4 + 255) / 256, 256>>>((const float4*)hs, (uint2*)hsH, (uint2*)hsL, n4);
    }
    // 0b) transpose+split weights
    {
        dim3 g(N1 / 32, KK / 32);
        tsplit_kernel<<<g, dim3(32, 8)>>>(w_qkv, wqH, wqL, KK, N1);
    }
    {
        dim3 g(DD / 32, KK / 32);
        tsplit_kernel<<<g, dim3(32, 8)>>>(w_proj, wpH, wpL, KK, DD);
    }
    // 1) QKV projection -> bf16 hi/lo (q pre-scaled)
    {
        dim3 g(N1 / 128, (MM + 255) / 256);
        gemm_mma_kernel<1><<<g, 256, gemm_smem>>>(hsH, hsL, wqH, wqL, b_qkv,
                                                  nullptr, qkvH, qkvL, MM, N1);
    }
    // 2) tensor-core flash attention -> bf16 hi/lo
    {
        dim3 g((SS + 127) / 128, HH, BB);
        attn_tc_kernel<<<g, 256, SM_ATT_TOTAL>>>(qkvH, qkvL, attH, attL);
    }
    // 3) output projection -> fp32
    {
        dim3 g(DD / 128, (MM + 255) / 256);
        gemm_mma_kernel<0><<<g, 256, gemm_smem>>>(attH, attL, wpH, wpL, b_proj,
                                                  out, nullptr, nullptr, MM, DD);
    }
}